// round 17
// baseline (speedup 1.0000x reference)
#include <cuda_runtime.h>
#include <cuda_fp16.h>
#include <cstdint>

// ---------------- problem constants ----------------------------------------
#define NN   100000   // batch rows
#define NNP  100096   // padded to 128
#define D_IN 500      // input features
#define KP1  512      // D_IN padded to MMA K granularity
#define HF   256      // hidden
#define MM   50000    // cluster rows
#define MMP  50048    // padded to 128
#define KC   40       // clusters
#define O2   1024     // OUT*OUT
#define EPSV 1e-5f

static inline int cdiv_h(int a, int b) { return (a + b - 1) / b; }

// ---------------- device scratch --------------------------------------------
__device__ __half g_H1[(size_t)NN * HF];    // raw GEMM1 out (fp16)
__device__ __half g_H2[(size_t)NN * HF];    // raw GEMM2 out (fp16)
__device__ float g_sum1[HF], g_sq1[HF], g_a1[HF], g_c1[HF];
__device__ float g_sum2[HF], g_sq2[HF], g_a2[HF], g_c2[HF];
__device__ float g_CFsum[KC * HF];
__device__ int   g_counts[KC];
__device__ int   g_labels[MM];
__device__ float g_PA[KC * O2];
__device__ float g_PB[KC * O2];

// Pre-tiled, SW128-swizzled fp16 operands.
// Tile (rowTile, kTile) of 128x64 halfs = 16 KB contiguous; SW128 inside.
__device__ __half g_xh [(size_t)NNP * KP1];
__device__ __half g_W1h[(size_t)HF * KP1];
__device__ __half g_A2h[(size_t)NNP * HF];
__device__ __half g_W2h[(size_t)HF * HF];
__device__ __half g_XCh[(size_t)MMP * HF];
__device__ __half g_WCh[(size_t)2048 * HF];

// ---------------- low-level helpers ------------------------------------------
__device__ __forceinline__ uint32_t smem_u32(const void* p) {
    uint32_t a;
    asm("{ .reg .u64 t; cvta.to.shared.u64 t, %1; cvt.u32.u64 %0, t; }"
        : "=r"(a) : "l"(p));
    return a;
}

__device__ __forceinline__ void bulkcp(uint32_t dst, const void* src,
                                       uint32_t bytes, uint32_t mbar) {
    asm volatile(
        "cp.async.bulk.shared::cluster.global.mbarrier::complete_tx::bytes "
        "[%0], [%1], %2, [%3];"
        :: "r"(dst), "l"(src), "r"(bytes), "r"(mbar) : "memory");
}

#define MBAR_INIT(addr, cnt) \
    asm volatile("mbarrier.init.shared.b64 [%0], %1;" \
                 :: "r"((uint32_t)(addr)), "r"((uint32_t)(cnt)) : "memory")
#define MBAR_EXPECT(addr, tx) \
    asm volatile("mbarrier.arrive.expect_tx.shared.b64 _, [%0], %1;" \
                 :: "r"((uint32_t)(addr)), "r"((uint32_t)(tx)) : "memory")
#define MBAR_WAIT(addr, parity) do {                                           \
    uint32_t _m = (uint32_t)(addr); uint32_t _p = (uint32_t)(parity);          \
    uint32_t _d;                                                               \
    asm volatile("{\n\t.reg .pred p;\n\t"                                      \
        "mbarrier.try_wait.parity.acquire.cta.shared::cta.b64 p, [%1], %2;\n\t"\
        "selp.b32 %0, 1, 0, p;\n\t}" : "=r"(_d) : "r"(_m), "r"(_p) : "memory");\
    if (!_d) {                                                                 \
        asm volatile("{\n\t.reg .pred P1;\n\t"                                 \
            "WL_%=:\n\t"                                                       \
            "mbarrier.try_wait.parity.acquire.cta.shared::cta.b64 P1, [%0], %1, 0x989680;\n\t" \
            "@P1 bra.uni WD_%=;\n\t"                                           \
            "bra.uni WL_%=;\n\t"                                               \
            "WD_%=:\n\t}" :: "r"(_m), "r"(_p) : "memory");                     \
    }                                                                          \
} while (0)

__device__ __forceinline__ void ldsm4(uint32_t* r, uint32_t addr) {
    asm volatile("ldmatrix.sync.aligned.m8n8.x4.shared.b16 {%0,%1,%2,%3}, [%4];"
                 : "=r"(r[0]), "=r"(r[1]), "=r"(r[2]), "=r"(r[3]) : "r"(addr));
}

__device__ __forceinline__ void mma16816(float* d, const uint32_t* a,
                                         uint32_t b0, uint32_t b1) {
    asm volatile(
        "mma.sync.aligned.m16n8k16.row.col.f32.f16.f16.f32 "
        "{%0,%1,%2,%3}, {%4,%5,%6,%7}, {%8,%9}, {%0,%1,%2,%3};"
        : "+f"(d[0]), "+f"(d[1]), "+f"(d[2]), "+f"(d[3])
        : "r"(a[0]), "r"(a[1]), "r"(a[2]), "r"(a[3]), "r"(b0), "r"(b1));
}

// Element offset inside the tiled+swizzled operand layout.
__device__ __forceinline__ size_t tileoff(int row, int k, int KT) {
    size_t base = ((size_t)((row >> 7) * KT + (k >> 6))) << 13;
    uint32_t boff = ((uint32_t)(row & 127) << 7) | ((uint32_t)(k & 63) << 1);
    uint32_t sw = boff ^ ((boff >> 3) & 0x70);
    return base + (sw >> 1);
}

__device__ __forceinline__ uint32_t swz(uint32_t boff) {
    return boff ^ ((boff >> 3) & 0x70);
}

#define TILE16K 16384
#define STG32K  32768
#define NSTAGE  3
#define SMEM_GG (NSTAGE * STG32K + 48)

// ---------------- GEMM engine (K=512 path, unchanged; GEMM1 only) -----------
__global__ void __launch_bounds__(256, 2)
k_bulkmma(const __half* __restrict__ Ah_, const __half* __restrict__ Bh_,
          int Mrows, int Ncols, int KT,
          const float* __restrict__ bias, __half* __restrict__ Hout) {
    extern __shared__ unsigned char smem[];
    const uint32_t sb = smem_u32(smem);
    const uint32_t mb = sb + NSTAGE * STG32K;
    const int tx = threadIdx.x;
    const int lane = tx & 31, wid = tx >> 5;
    const int warpM = wid & 3;
    const int warpN = wid >> 2;
    const int rowBase = blockIdx.y * 128;
    const int colBase = blockIdx.x * 128;

    if (tx == 0) {
#pragma unroll
        for (int s = 0; s < NSTAGE; s++) MBAR_INIT(mb + 8 * s, 1);
    }
    __syncthreads();

    const size_t aBase = ((size_t)blockIdx.y * KT) << 13;
    const size_t bBase = ((size_t)blockIdx.x * KT) << 13;

    if (tx == 0) {
        const int pre = (KT < NSTAGE) ? KT : NSTAGE;
        for (int s = 0; s < pre; s++) {
            MBAR_EXPECT(mb + 8 * s, STG32K);
            uint32_t d = sb + (uint32_t)s * STG32K;
            bulkcp(d + 0 * TILE16K, Ah_ + aBase + ((size_t)s << 13), TILE16K, mb + 8 * s);
            bulkcp(d + 1 * TILE16K, Bh_ + bBase + ((size_t)s << 13), TILE16K, mb + 8 * s);
        }
    }

    float acc[2][8][4];
#pragma unroll
    for (int i = 0; i < 2; i++)
#pragma unroll
        for (int j = 0; j < 8; j++)
#pragma unroll
            for (int q = 0; q < 4; q++) acc[i][j][q] = 0.f;

    int ph[NSTAGE] = {0, 0, 0};
    for (int c = 0; c < KT; c++) {
        const int s = c % NSTAGE;
        MBAR_WAIT(mb + 8 * s, ph[s]);
        ph[s] ^= 1;
        const uint32_t stg = sb + (uint32_t)s * STG32K;
#pragma unroll
        for (int ks = 0; ks < 4; ks++) {
            const int k0 = ks * 16;
            uint32_t ah[2][4], bh[4][4];
#pragma unroll
            for (int mf = 0; mf < 2; mf++) {
                uint32_t boff = ((uint32_t)(warpM * 32 + mf * 16 + (lane & 15)) << 7) |
                                ((uint32_t)(k0 + (lane >> 4) * 8) << 1);
                ldsm4(ah[mf], stg + 0 * TILE16K + swz(boff));
            }
            {
                const int grp = lane >> 3, rin = lane & 7;
#pragma unroll
                for (int p = 0; p < 4; p++) {
                    uint32_t boff = ((uint32_t)(warpN * 64 + p * 16 + (grp >> 1) * 8 + rin) << 7) |
                                    ((uint32_t)(k0 + (grp & 1) * 8) << 1);
                    ldsm4(bh[p], stg + 1 * TILE16K + swz(boff));
                }
            }
#pragma unroll
            for (int p = 0; p < 4; p++)
#pragma unroll
                for (int mf = 0; mf < 2; mf++) {
                    mma16816(acc[mf][2 * p + 0], ah[mf], bh[p][0], bh[p][1]);
                    mma16816(acc[mf][2 * p + 1], ah[mf], bh[p][2], bh[p][3]);
                }
        }
        __syncthreads();
        if (c + NSTAGE < KT && tx == 0) {
            const int cn = c + NSTAGE;
            MBAR_EXPECT(mb + 8 * s, STG32K);
            uint32_t d = sb + (uint32_t)s * STG32K;
            bulkcp(d + 0 * TILE16K, Ah_ + aBase + ((size_t)cn << 13), TILE16K, mb + 8 * s);
            bulkcp(d + 1 * TILE16K, Bh_ + bBase + ((size_t)cn << 13), TILE16K, mb + 8 * s);
        }
    }

#pragma unroll
    for (int mf = 0; mf < 2; mf++) {
#pragma unroll
        for (int half = 0; half < 2; half++) {
            const int r = rowBase + warpM * 32 + mf * 16 + (lane >> 2) + half * 8;
            if (r >= Mrows) continue;
            __half* cp = Hout + (size_t)r * Ncols;
#pragma unroll
            for (int nf = 0; nf < 8; nf++) {
                const int cc = colBase + warpN * 64 + nf * 8 + (lane & 3) * 2;
                float2 b = *(const float2*)(bias + cc);
                __half2 v;
                v.x = __float2half(acc[mf][nf][half * 2 + 0] + b.x);
                v.y = __float2half(acc[mf][nf][half * 2 + 1] + b.y);
                *(__half2*)(cp + cc) = v;
            }
        }
    }
}

// ---------------- B-resident GEMM (K=256 layers: GEMM2 / GEMM3) -------------
// B column-block (4 chunks = 64 KB) loaded ONCE per CTA; A streamed through a
// 3-stage 16 KB pipe; R row-tiles per CTA amortize B-load + prologue, and each
// tile's epilogue overlaps the next tile's A prefetch.
// SMEM: B 64 KB + A 48 KB + mbars = 112.1 KB -> 2 CTAs/SM (224 <= 228 KB).
// MODE 0: Hout = fp16(acc + bias)   MODE 1: +PB/PA[label], 2M-row fp32 out.
#define SMEM_B64 65536
#define SMEM_BR  (SMEM_B64 + NSTAGE * TILE16K + 64)

template <int MODE>
__global__ void __launch_bounds__(256, 2)
k_bres(const __half* __restrict__ Ah_, const __half* __restrict__ Bh_,
       int Mrows, int aTiles, int R, int Ncols,
       const float* __restrict__ bias, __half* __restrict__ Hout,
       const int* __restrict__ labels, const float* __restrict__ PA,
       const float* __restrict__ PB, float* __restrict__ out) {
    extern __shared__ unsigned char smem[];
    const uint32_t sb = smem_u32(smem);            // B region (4 x 16 KB)
    const uint32_t as = sb + SMEM_B64;             // A stages (3 x 16 KB)
    const uint32_t mb = as + NSTAGE * TILE16K;     // bmbar +0, ambar s at +8+8s
    const int tx = threadIdx.x;
    const int lane = tx & 31, wid = tx >> 5;
    const int warpM = wid & 3;
    const int warpN = wid >> 2;
    const int colBase = blockIdx.x * 128;
    const int tile0 = blockIdx.y * R;
    const int NCH = R * 4;                         // total A chunks

    if (tx == 0) {
        MBAR_INIT(mb + 0, 1);
#pragma unroll
        for (int s = 0; s < NSTAGE; s++) MBAR_INIT(mb + 8 + 8 * s, 1);
    }
    __syncthreads();

    if (tx == 0) {
        // B: whole K (4 chunks) once
        const size_t bBase = ((size_t)blockIdx.x * 4) << 13;
        MBAR_EXPECT(mb + 0, SMEM_B64);
        for (int c = 0; c < 4; c++)
            bulkcp(sb + (uint32_t)c * TILE16K, Bh_ + bBase + ((size_t)c << 13),
                   TILE16K, mb + 0);
        // A: prefetch first stages
        const int pre = (NCH < NSTAGE) ? NCH : NSTAGE;
        for (int g = 0; g < pre; g++) {
            int tt = tile0 + (g >> 2);
            if (tt >= aTiles) tt = aTiles - 1;     // clamp (dummy tile)
            MBAR_EXPECT(mb + 8 + 8 * g, TILE16K);
            bulkcp(as + (uint32_t)g * TILE16K,
                   Ah_ + (((size_t)tt * 4 + (g & 3)) << 13), TILE16K, mb + 8 + 8 * g);
        }
    }
    MBAR_WAIT(mb + 0, 0);                          // B ready

    int ph[NSTAGE] = {0, 0, 0};
    for (int rb = 0; rb < R; rb++) {
        const int tileIdx = tile0 + rb;
        const bool live = tileIdx < aTiles;
        const int rowBase = tileIdx * 128;

        float acc[2][8][4];
#pragma unroll
        for (int i = 0; i < 2; i++)
#pragma unroll
            for (int j = 0; j < 8; j++)
#pragma unroll
                for (int q = 0; q < 4; q++) acc[i][j][q] = 0.f;

        for (int c = 0; c < 4; c++) {
            const int g = rb * 4 + c;
            const int s = g % NSTAGE;
            MBAR_WAIT(mb + 8 + 8 * s, ph[s]);
            ph[s] ^= 1;
            const uint32_t astg = as + (uint32_t)s * TILE16K;
            const uint32_t bstg = sb + (uint32_t)c * TILE16K;
            if (live) {
#pragma unroll
                for (int ks = 0; ks < 4; ks++) {
                    const int k0 = ks * 16;
                    uint32_t ah[2][4], bh[4][4];
#pragma unroll
                    for (int mf = 0; mf < 2; mf++) {
                        uint32_t boff = ((uint32_t)(warpM * 32 + mf * 16 + (lane & 15)) << 7) |
                                        ((uint32_t)(k0 + (lane >> 4) * 8) << 1);
                        ldsm4(ah[mf], astg + swz(boff));
                    }
                    {
                        const int grp = lane >> 3, rin = lane & 7;
#pragma unroll
                        for (int p = 0; p < 4; p++) {
                            uint32_t boff = ((uint32_t)(warpN * 64 + p * 16 + (grp >> 1) * 8 + rin) << 7) |
                                            ((uint32_t)(k0 + (grp & 1) * 8) << 1);
                            ldsm4(bh[p], bstg + swz(boff));
                        }
                    }
#pragma unroll
                    for (int p = 0; p < 4; p++)
#pragma unroll
                        for (int mf = 0; mf < 2; mf++) {
                            mma16816(acc[mf][2 * p + 0], ah[mf], bh[p][0], bh[p][1]);
                            mma16816(acc[mf][2 * p + 1], ah[mf], bh[p][2], bh[p][3]);
                        }
                }
            }
            __syncthreads();
            if (g + NSTAGE < NCH && tx == 0) {
                const int gn = g + NSTAGE;
                int tt = tile0 + (gn >> 2);
                if (tt >= aTiles) tt = aTiles - 1;
                MBAR_EXPECT(mb + 8 + 8 * s, TILE16K);
                bulkcp(as + (uint32_t)s * TILE16K,
                       Ah_ + (((size_t)tt * 4 + (gn & 3)) << 13), TILE16K, mb + 8 + 8 * s);
            }
        }

        if (!live) continue;
        // epilogue (identical layout/math to the proven kernel)
#pragma unroll
        for (int mf = 0; mf < 2; mf++) {
#pragma unroll
            for (int half = 0; half < 2; half++) {
                const int r = rowBase + warpM * 32 + mf * 16 + (lane >> 2) + half * 8;
                if (r >= Mrows) continue;
                if (MODE == 0) {
                    __half* cp = Hout + (size_t)r * Ncols;
#pragma unroll
                    for (int nf = 0; nf < 8; nf++) {
                        const int cc = colBase + warpN * 64 + nf * 8 + (lane & 3) * 2;
                        float2 b = *(const float2*)(bias + cc);
                        __half2 v;
                        v.x = __float2half(acc[mf][nf][half * 2 + 0] + b.x);
                        v.y = __float2half(acc[mf][nf][half * 2 + 1] + b.y);
                        *(__half2*)(cp + cc) = v;
                    }
                } else {
                    const bool hB = colBase >= 1024;
                    const int lab = labels[r];
                    const float* P = hB ? PA : PB;
                    const float* pl = P + (size_t)lab * O2;
                    float* op = out + ((size_t)r + (hB ? (size_t)MM : 0)) * O2;
                    const int cB = (colBase & 1023) + warpN * 64;
#pragma unroll
                    for (int nf = 0; nf < 8; nf++) {
                        const int col = cB + nf * 8 + (lane & 3) * 2;
                        float2 p = *(const float2*)(pl + col);
                        float2 v;
                        v.x = acc[mf][nf][half * 2 + 0] + p.x;
                        v.y = acc[mf][nf][half * 2 + 1] + p.y;
                        *(float2*)(op + col) = v;
                    }
                }
            }
        }
    }
}

// ---------------- split kernels: fp32 -> tiled swizzled fp16 ----------------
__global__ void k_split_a(const float* __restrict__ src,
                          __half* __restrict__ dst,
                          int rowsSrc, int colsSrc, int K8, int KT,
                          long long total) {
    long long idx = blockIdx.x * (long long)blockDim.x + threadIdx.x;
    if (idx >= total) return;
    int row = (int)(idx / K8);
    int k   = (int)(idx % K8) * 8;
    __half h8[8];
    if (row < rowsSrc && k + 8 <= colsSrc) {
        const float4* sp = (const float4*)(src + (size_t)row * colsSrc + k);
        float4 v0 = sp[0], v1 = sp[1];
        h8[0] = __float2half(v0.x); h8[1] = __float2half(v0.y);
        h8[2] = __float2half(v0.z); h8[3] = __float2half(v0.w);
        h8[4] = __float2half(v1.x); h8[5] = __float2half(v1.y);
        h8[6] = __float2half(v1.z); h8[7] = __float2half(v1.w);
    } else {
#pragma unroll
        for (int j = 0; j < 8; j++) {
            float v = 0.f;
            if (row < rowsSrc && k + j < colsSrc)
                v = src[(size_t)row * colsSrc + k + j];
            h8[j] = __float2half(v);
        }
    }
    *(uint4*)(dst + tileoff(row, k, KT)) = *(uint4*)h8;
}

__global__ void k_split_aff_a(const __half* __restrict__ src,
                              const float* __restrict__ aa, const float* __restrict__ cc,
                              __half* __restrict__ dst,
                              int rowsSrc, long long total) {
    long long idx = blockIdx.x * (long long)blockDim.x + threadIdx.x;
    if (idx >= total) return;
    int row = (int)(idx / (HF / 8));
    int k   = (int)(idx % (HF / 8)) * 8;
    __half h8[8];
    if (row < rowsSrc) {
        uint4 raw = *(const uint4*)(src + (size_t)row * HF + k);
        const __half* hp = (const __half*)&raw;
#pragma unroll
        for (int j = 0; j < 8; j++) {
            float v = fmaxf(fmaf(aa[k + j], __half2float(hp[j]), cc[k + j]), 0.f);
            h8[j] = __float2half(v);
        }
    } else {
#pragma unroll
        for (int j = 0; j < 8; j++) h8[j] = __float2half(0.f);
    }
    *(uint4*)(dst + tileoff(row, k, HF / 64)) = *(uint4*)h8;
}

__global__ void k_split_wcat(const float* __restrict__ Wfc,
                             __half* __restrict__ dst) {
    int idx = blockIdx.x * blockDim.x + threadIdx.x;
    if (idx >= 2048 * (HF / 8)) return;
    int o = idx / (HF / 8);
    int k = (idx % (HF / 8)) * 8;
    const float* w = (o < 1024) ? (Wfc + (size_t)o * (2 * HF))
                                : (Wfc + (size_t)(o - 1024) * (2 * HF) + HF);
    const float4* sp = (const float4*)(w + k);
    float4 v0 = sp[0], v1 = sp[1];
    __half h8[8];
    h8[0] = __float2half(v0.x); h8[1] = __float2half(v0.y);
    h8[2] = __float2half(v0.z); h8[3] = __float2half(v0.w);
    h8[4] = __float2half(v1.x); h8[5] = __float2half(v1.y);
    h8[6] = __float2half(v1.z); h8[7] = __float2half(v1.w);
    *(uint4*)(dst + tileoff(o, k, HF / 64)) = *(uint4*)h8;
}

// ---------------- stats / labels ---------------------------------------------
__global__ void k_zero(float* s1, float* q1, float* s2, float* q2,
                       float* cfs, int* cnt) {
    int t = blockIdx.x * blockDim.x + threadIdx.x;
    if (t < HF) { s1[t] = 0.f; q1[t] = 0.f; s2[t] = 0.f; q2[t] = 0.f; }
    if (t < KC) cnt[t] = 0;
    if (t < KC * HF) cfs[t] = 0.f;
}

__global__ void k_colstats(const __half* __restrict__ H,
                           float* __restrict__ sum, float* __restrict__ sq) {
    __shared__ float ssum[8][HF];
    __shared__ float ssq[8][HF];
    const int t = threadIdx.x;
    const int c8 = t & 31;
    const int rsub = t >> 5;
    const int per = (NN + gridDim.x - 1) / gridDim.x;
    const int r0 = blockIdx.x * per;
    const int r1 = min(NN, r0 + per);
    float s[8], q[8];
#pragma unroll
    for (int j = 0; j < 8; j++) { s[j] = 0.f; q[j] = 0.f; }
    for (int r = r0 + rsub; r < r1; r += 8) {
        uint4 raw = *(const uint4*)(H + (size_t)r * HF + c8 * 8);
        const __half* hp = (const __half*)&raw;
#pragma unroll
        for (int j = 0; j < 8; j++) {
            float v = __half2float(hp[j]);
            s[j] += v;
            q[j] = fmaf(v, v, q[j]);
        }
    }
#pragma unroll
    for (int j = 0; j < 8; j++) {
        ssum[rsub][c8 * 8 + j] = s[j];
        ssq[rsub][c8 * 8 + j] = q[j];
    }
    __syncthreads();
    float ts = 0.f, tq = 0.f;
#pragma unroll
    for (int i = 0; i < 8; i++) { ts += ssum[i][t]; tq += ssq[i][t]; }
    atomicAdd(&sum[t], ts);
    atomicAdd(&sq[t], tq);
}

__global__ void k_finalize(const float* __restrict__ sum, const float* __restrict__ sq,
                           const float* __restrict__ gam, const float* __restrict__ bet,
                           float* __restrict__ a, float* __restrict__ c) {
    int t = threadIdx.x;
    const float invN = 1.0f / (float)NN;
    float mean = sum[t] * invN;
    float var  = sq[t] * invN - mean * mean;
    float inv  = rsqrtf(var + EPSV);
    float aa   = gam[t] * inv;
    a[t] = aa;
    c[t] = bet[t] - mean * aa;
}

__global__ void k_labels(const float* __restrict__ cid,
                         int* __restrict__ labels, int* __restrict__ cnt) {
    int m = blockIdx.x * blockDim.x + threadIdx.x;
    if (m >= MM) return;
    const float* row = cid + (size_t)m * KC;
    int best = 0;
    float bv = row[0];
#pragma unroll
    for (int k = 1; k < KC; k++) {
        float v = row[k];
        if (v > bv) { bv = v; best = k; }
    }
    labels[m] = best;
    atomicAdd(&cnt[best], 1);
}

// ---------------- fused XC pipeline ------------------------------------------
__global__ void k_xc_fused(const __half* __restrict__ H2,
                           const int* __restrict__ ci,
                           const int* __restrict__ labels,
                           const float* __restrict__ a2,
                           const float* __restrict__ c2,
                           __half* __restrict__ XCh,
                           float* __restrict__ CFsum) {
    __shared__ float acc[KC * HF];
    const int t = threadIdx.x;
    for (int i = t; i < KC * HF; i += 256) acc[i] = 0.f;
    __syncthreads();
    const float av = a2[t], cv = c2[t];
    const int per = (MMP + gridDim.x - 1) / gridDim.x;
    const int m0 = blockIdx.x * per;
    const int m1 = min(MMP, m0 + per);
    for (int m = m0; m < m1; m++) {
        float v = 0.f;
        if (m < MM) {
            const int r = ci[m];
            v = fmaxf(fmaf(av, __half2float(H2[(size_t)r * HF + t]), cv), 0.f);
            acc[labels[m] * HF + t] += v;
        }
        XCh[tileoff(m, t, HF / 64)] = __float2half(v);
    }
    __syncthreads();
    for (int i = t; i < KC * HF; i += 256) atomicAdd(&CFsum[i], acc[i]);
}

__global__ void k_ptab(const float* __restrict__ Wfc, const float* __restrict__ bfc,
                       const float* __restrict__ CFsum, const int* __restrict__ cnt,
                       float* __restrict__ PA, float* __restrict__ PB) {
    __shared__ float cf[HF];
    int k = blockIdx.y;
    int t = threadIdx.x;
    float cnv = (float)cnt[k];
    cf[t] = CFsum[k * HF + t] / cnv;
    __syncthreads();
    int o = blockIdx.x * 256 + t;
    const float* w = Wfc + (size_t)o * (2 * HF);
    float sa = 0.f, sb = 0.f;
#pragma unroll 4
    for (int j = 0; j < HF; j++) {
        float c = cf[j];
        sa = fmaf(c, w[j], sa);
        sb = fmaf(c, w[HF + j], sb);
    }
    float bb = bfc[o];
    PA[k * O2 + o] = sa + bb;
    PB[k * O2 + o] = sb + bb;
}

// ---------------- host launcher ---------------------------------------------
extern "C" void kernel_launch(void* const* d_in, const int* in_sizes, int n_in,
                              void* d_out, int out_size) {
    const float* x    = (const float*)d_in[0];
    const float* cid  = (const float*)d_in[1];
    const int*   cidx = (const int*)  d_in[2];
    const float* W1   = (const float*)d_in[3];
    const float* b1   = (const float*)d_in[4];
    const float* g1   = (const float*)d_in[5];
    const float* be1  = (const float*)d_in[6];
    const float* W2   = (const float*)d_in[7];
    const float* b2   = (const float*)d_in[8];
    const float* g2   = (const float*)d_in[9];
    const float* be2  = (const float*)d_in[10];
    const float* Wfc  = (const float*)d_in[11];
    const float* bfc  = (const float*)d_in[12];
    float* out = (float*)d_out;

    static bool inited = false;
    static float *sum1, *sq1, *a1, *c1, *sum2, *sq2, *a2, *c2, *CFs, *PA, *PB;
    static int *cnt, *labs;
    static __half *H1, *H2, *xh, *W1h, *A2h, *W2h, *XCh, *WCh;
    if (!inited) {
        inited = true;
        cudaGetSymbolAddress((void**)&H1,   g_H1);
        cudaGetSymbolAddress((void**)&H2,   g_H2);
        cudaGetSymbolAddress((void**)&sum1, g_sum1);
        cudaGetSymbolAddress((void**)&sq1,  g_sq1);
        cudaGetSymbolAddress((void**)&a1,   g_a1);
        cudaGetSymbolAddress((void**)&c1,   g_c1);
        cudaGetSymbolAddress((void**)&sum2, g_sum2);
        cudaGetSymbolAddress((void**)&sq2,  g_sq2);
        cudaGetSymbolAddress((void**)&a2,   g_a2);
        cudaGetSymbolAddress((void**)&c2,   g_c2);
        cudaGetSymbolAddress((void**)&CFs,  g_CFsum);
        cudaGetSymbolAddress((void**)&PA,   g_PA);
        cudaGetSymbolAddress((void**)&PB,   g_PB);
        cudaGetSymbolAddress((void**)&cnt,  g_counts);
        cudaGetSymbolAddress((void**)&labs, g_labels);
        cudaGetSymbolAddress((void**)&xh,   g_xh);
        cudaGetSymbolAddress((void**)&W1h,  g_W1h);
        cudaGetSymbolAddress((void**)&A2h,  g_A2h);
        cudaGetSymbolAddress((void**)&W2h,  g_W2h);
        cudaGetSymbolAddress((void**)&XCh,  g_XCh);
        cudaGetSymbolAddress((void**)&WCh,  g_WCh);
        cudaFuncSetAttribute(k_bulkmma,
                             cudaFuncAttributeMaxDynamicSharedMemorySize, SMEM_GG);
        cudaFuncSetAttribute(k_bres<0>,
                             cudaFuncAttributeMaxDynamicSharedMemorySize, SMEM_BR);
        cudaFuncSetAttribute(k_bres<1>,
                             cudaFuncAttributeMaxDynamicSharedMemorySize, SMEM_BR);
    }

    // 0) zero accumulators
    k_zero<<<40, 256>>>(sum1, sq1, sum2, sq2, CFs, cnt);

    // 1) x -> tiled fp16
    {
        long long t = (long long)NNP * (KP1 / 8);
        k_split_a<<<(int)((t + 255) / 256), 256>>>(x, xh,
                                                   NN, D_IN, KP1 / 8, KP1 / 64, t);
    }
    // 2) W1 -> tiled fp16
    {
        long long t1 = (long long)HF * (KP1 / 8);
        k_split_a<<<cdiv_h((int)t1, 256), 256>>>(W1, W1h,
                                                 HF, D_IN, KP1 / 8, KP1 / 64, t1);
    }
    // 3) GEMM1: H1 = fp16(x @ W1^T + b1)       <-- ncu-profiled slot
    {
        dim3 grid(HF / 128, NNP / 128);
        k_bulkmma<<<grid, 256, SMEM_GG>>>(xh, W1h, NN, HF, KP1 / 64, b1, H1);
    }
    // 4) BN1 stats
    k_colstats<<<512, 256>>>(H1, sum1, sq1);
    k_finalize<<<1, 256>>>(sum1, sq1, g1, be1, a1, c1);

    // 5) W2 -> tiled fp16; A2 = relu(a1*H1 + c1); GEMM2 (B-resident, R=2)
    {
        long long t2 = (long long)HF * (HF / 8);
        k_split_a<<<cdiv_h((int)t2, 256), 256>>>(W2, W2h,
                                                 HF, HF, HF / 8, HF / 64, t2);
        long long t = (long long)NNP * (HF / 8);
        k_split_aff_a<<<(int)((t + 255) / 256), 256>>>(H1, a1, c1, A2h, NN, t);
        dim3 grid(HF / 128, (NNP / 128) / 2);   // 782 tiles, R=2 -> 391
        k_bres<0><<<grid, 256, SMEM_BR>>>(A2h, W2h, NN, NNP / 128, 2, HF,
                                          b2, H2, nullptr, nullptr, nullptr, nullptr);
    }
    // 6) BN2 stats
    k_colstats<<<512, 256>>>(H2, sum2, sq2);
    k_finalize<<<1, 256>>>(sum2, sq2, g2, be2, a2, c2);

    // 7) labels + counts
    k_labels<<<cdiv_h(MM, 256), 256>>>(cid, labs, cnt);

    // 8) fused: XCh (tiled fp16) + cluster feature sums
    k_xc_fused<<<256, 256>>>(H2, cidx, labs, a2, c2, XCh, CFs);

    // 9) Wcat -> tiled fp16; PA/PB tables
    k_split_wcat<<<cdiv_h(2048 * (HF / 8), 256), 256>>>(Wfc, WCh);
    {
        dim3 grid(O2 / 256, KC);
        k_ptab<<<grid, 256>>>(Wfc, bfc, CFs, cnt, PA, PB);
    }

    // 10) final GEMM (B-resident, R=4): Y = XC @ Wcat^T + tables
    {
        dim3 grid(2048 / 128, cdiv_h(MMP / 128, 4));  // 391 tiles, R=4 -> 98
        k_bres<1><<<grid, 256, SMEM_BR>>>(XCh, WCh, MM, MMP / 128, 4, 0,
                                          nullptr, nullptr, labs, PA, PB, out);
    }
}